// round 17
// baseline (speedup 1.0000x reference)
#include <cuda_runtime.h>
#include <cuda_fp16.h>
#include <cstdint>

// Problem dims
#define NBATCH 32
#define NT     2048
#define ND     512
#define NU     512

#define LDA  520    // A smem row stride in fp16 (1040B; 260 words mod 32 = 4 -> conflict-free)
#define LDB  40     // B smem row stride in fp16 (80B; 20 words mod 32 -> distinct row phases)
#define BUFB (256 * LDB * 2)   // 20480 B per B buffer (256 n-rows x 32 k)
#define NCH  32     // chunks: 2 n-blocks x 16 k-chunks (32k each)
#define MAXC 16     // max argmax candidates per batch

// ---------------- device scratch (no allocs allowed) ----------------
__device__ float              g_u[NBATCH * NT];    // raw scores u[b,t] (pre-mask)
__device__ __half             g_w1t[NU * ND];      // W1 transposed [n][k] fp16
__device__ float              g_w2q[NBATCH * NU];  // query @ W2 (atomic split-k)
__device__ int                g_cand[NBATCH * MAXC];
__device__ int                g_ncand[NBATCH];
__device__ float              g_score[NBATCH * MAXC];
__device__ unsigned long long g_best[NBATCH];      // packed (score_key << 32) | (2047 - t)

// ---------------- asm helpers ----------------
__device__ __forceinline__ uint32_t smem_u32(const void* p) {
    uint32_t a;
    asm("{ .reg .u64 t; cvta.to.shared.u64 t, %1; cvt.u32.u64 %0, t; }" : "=r"(a) : "l"(p));
    return a;
}
__device__ __forceinline__ void ldsm4(uint32_t& r0, uint32_t& r1, uint32_t& r2,
                                      uint32_t& r3, uint32_t addr) {
    asm volatile("ldmatrix.sync.aligned.m8n8.x4.shared.b16 {%0,%1,%2,%3}, [%4];"
                 : "=r"(r0), "=r"(r1), "=r"(r2), "=r"(r3) : "r"(addr));
}
__device__ __forceinline__ void cpasync16(uint32_t dst, const void* src) {
    asm volatile("cp.async.cg.shared.global [%0], [%1], 16;" :: "r"(dst), "l"(src));
}
#define CP_COMMIT() asm volatile("cp.async.commit_group;")
#define CP_WAIT0()  asm volatile("cp.async.wait_group 0;")

__device__ __forceinline__ void mma16816(float* c, uint32_t a0, uint32_t a1,
                                         uint32_t a2, uint32_t a3,
                                         uint32_t b0, uint32_t b1) {
    asm volatile(
        "mma.sync.aligned.m16n8k16.row.col.f32.f16.f16.f32 "
        "{%0,%1,%2,%3}, {%4,%5,%6,%7}, {%8,%9}, {%0,%1,%2,%3};\n"
        : "+f"(c[0]), "+f"(c[1]), "+f"(c[2]), "+f"(c[3])
        : "r"(a0), "r"(a1), "r"(a2), "r"(a3), "r"(b0), "r"(b1));
}

// HW tanh (sm_75+): single MUFU op, abs err ~1e-4 — inside error budget
__device__ __forceinline__ float tanh_approx(float x) {
    float y;
    asm("tanh.approx.f32 %0, %1;" : "=f"(y) : "f"(x));
    return y;
}

// sortable key for (maximize score, tie -> lower t)
__device__ __forceinline__ unsigned long long pack_key(float s, int t) {
    uint32_t u = __float_as_uint(s);
    uint32_t m = (u & 0x80000000u) ? ~u : (u | 0x80000000u);
    return ((unsigned long long)m << 32) | (unsigned)(2047 - t);
}

// ---------------- smem layout for attn_main (64-row CTA) ----------------
#define SM_A     0                          // 64 x LDA fp16 = 66560
#define SM_B     (64 * LDA * 2)             // 2 x 20480 = 40960
#define SM_W2Q   (SM_B + 2 * BUFB)          // 512 f32
#define SM_V     (SM_W2Q + 512 * 4)         // 512 f32
#define SM_RED   (SM_V + 512 * 4)           // 256 f32 (4 col-groups x 64 rows)
#define SMEM_BYTES (SM_RED + 256 * 4)       // 112640 -> 2 CTAs/SM fit

// ==================== kernel: W1 transpose + fp16 convert (tiled) ====================
__global__ void prep_w1t(const float* __restrict__ W1) {
    __shared__ float t[32][33];
    int n0 = blockIdx.x * 32, k0 = blockIdx.y * 32;
    for (int i = threadIdx.y; i < 32; i += 8)
        t[i][threadIdx.x] = W1[(size_t)(k0 + i) * NU + n0 + threadIdx.x];
    __syncthreads();
    for (int i = threadIdx.y; i < 32; i += 8)
        g_w1t[(size_t)(n0 + i) * ND + k0 + threadIdx.x] = __float2half_rn(t[threadIdx.x][i]);
}

// ==================== kernel: zero accumulator scratch ====================
__global__ void init_kernel() {
    int i = blockIdx.x * 512 + threadIdx.x;          // grid 32 -> 16384
    if (i < NBATCH * NU)   g_w2q[i]  = 0.f;
    if (i < NBATCH * MAXC) g_score[i] = 0.f;
    if (i < NBATCH)        g_best[i]  = 0ull;
}

// ==================== kernel: w2q = query @ W2 (split-k GEMM, W2 read once) ======
// grid (8 n-tiles, 4 k-slices), block 64. Thread handles one n, 32 batch accumulators.
__global__ void __launch_bounds__(64)
prep_w2q(const float* __restrict__ query, const float* __restrict__ W2) {
    __shared__ float q[32 * 128];                    // q[b][d0..d0+127]
    const int tx = threadIdx.x;
    const int n  = blockIdx.x * 64 + tx;
    const int d0 = blockIdx.y * 128;

    for (int i = tx; i < 32 * 128; i += 64) {
        int b = i >> 7, dd = i & 127;
        q[i] = query[b * ND + d0 + dd];
    }
    __syncthreads();

    float acc[32];
#pragma unroll
    for (int b = 0; b < 32; b++) acc[b] = 0.f;
    for (int d = 0; d < 128; d++) {
        float w = W2[(size_t)(d0 + d) * NU + n];
#pragma unroll
        for (int b = 0; b < 32; b++) acc[b] += q[b * 128 + d] * w;
    }
#pragma unroll
    for (int b = 0; b < 32; b++) atomicAdd(&g_w2q[b * NU + n], acc[b]);
}

// ==================== kernel: fused GEMM + tanh + V-dot ====================
// 64-row CTAs, 256 threads = 8 warps as 2x4 grid of 32x64 warp tiles; 2 CTAs/SM.
// B streamed as 32 chunks (2 n-blocks of 256 x 16 k-chunks of 32k), double-buffered.
__global__ void __launch_bounds__(256, 2)
attn_main(const float* __restrict__ value, const float* __restrict__ Vvec) {
    extern __shared__ char smem[];
    __half* sA    = reinterpret_cast<__half*>(smem + SM_A);
    float*  s_w2q = reinterpret_cast<float*>(smem + SM_W2Q);
    float*  s_V   = reinterpret_cast<float*>(smem + SM_V);
    float*  s_red = reinterpret_cast<float*>(smem + SM_RED);

    const uint32_t sA_u = smem_u32(smem) + SM_A;
    const uint32_t sB_u = smem_u32(smem) + SM_B;

    const int tid  = threadIdx.x;
    const int wid  = tid >> 5;
    const int lane = tid & 31;
    const int row0 = blockIdx.x * 64;                // global (b*T + t) row
    const int b    = row0 >> 11;

    // ---- prefetch B chunk 0 (n 0..255, k 0..31) into buf 0 ----
    {
        const char* bsrc = reinterpret_cast<const char*>(g_w1t);
#pragma unroll
        for (int j = 0; j < 4; j++) {
            int i = tid + j * 256;                   // 0..1023: 256 rows x 4 x 16B
            int r = i >> 2, c16 = i & 3;
            cpasync16(sB_u + r * (LDB * 2) + c16 * 16, bsrc + (size_t)r * 1024 + c16 * 16);
        }
        CP_COMMIT();
    }

    // ---- stage A: value[row0:row0+64, :] fp32 -> fp16 smem (padded rows) ----
    const float4* vsrc = reinterpret_cast<const float4*>(value + (size_t)row0 * ND);
    for (int i = tid; i < 64 * 128; i += 256) {      // 8192 float4s
        int r = i >> 7, c4 = i & 127;
        float4 v = vsrc[r * 128 + c4];
        __half2 lo = __floats2half2_rn(v.x, v.y);
        __half2 hi = __floats2half2_rn(v.z, v.w);
        uint2 pk;
        pk.x = *reinterpret_cast<uint32_t*>(&lo);
        pk.y = *reinterpret_cast<uint32_t*>(&hi);
        *reinterpret_cast<uint2*>(sA + (size_t)r * LDA + c4 * 4) = pk;
    }
    for (int i = tid; i < 512; i += 256) {
        s_w2q[i] = g_w2q[b * NU + i];
        s_V[i]   = Vvec[i];
    }
    CP_WAIT0();
    __syncthreads();                                 // B0 + A ready

    const int rg  = wid & 1;                         // row group: m0 = rg*32
    const int cgw = wid >> 1;                        // col group: n0w = cgw*64
    const int gq  = lane >> 2, tq = lane & 3;
    const int m0  = rg * 32;
    const int n0w = cgw * 64;

    const int rowA = m0 + (lane & 7) + ((lane >> 3) & 1) * 8;
    const uint32_t addrA0 = sA_u + (uint32_t)(rowA * LDA + (lane >> 4) * 8) * 2;
    const int rowB = n0w + (lane & 7) + ((lane >> 4) & 1) * 8;
    const uint32_t addrB0_rel = (uint32_t)(rowB * LDB + ((lane >> 3) & 1) * 8) * 2;

    float rsum[4] = {0.f, 0.f, 0.f, 0.f};
    float acc[2][8][4];                              // [m-frag][n-frag][quad]

    for (int ch = 0; ch < NCH; ch++) {
        const int nc = ch >> 4, kc = ch & 15;
        if (kc == 0) {
#pragma unroll
            for (int mi = 0; mi < 2; mi++)
#pragma unroll
                for (int ni = 0; ni < 8; ni++)
#pragma unroll
                    for (int j = 0; j < 4; j++) acc[mi][ni][j] = 0.f;
        }

        // prefetch B chunk ch+1 into the other buffer
        if (ch + 1 < NCH) {
            int nn = (ch + 1) >> 4, kk = (ch + 1) & 15;
            const char* bsrc = reinterpret_cast<const char*>(g_w1t)
                             + (size_t)nn * 262144 + (size_t)kk * 64;
            uint32_t bufo = ((ch + 1) & 1) * BUFB;
#pragma unroll
            for (int j = 0; j < 4; j++) {
                int i = tid + j * 256;
                int r = i >> 2, c16 = i & 3;
                cpasync16(sB_u + bufo + r * (LDB * 2) + c16 * 16,
                          bsrc + (size_t)r * 1024 + c16 * 16);
            }
            CP_COMMIT();
        }

        // ---- compute chunk (nc, kc): 2 k-steps of 16 ----
        const uint32_t aK = addrA0 + kc * 64;        // kc*32 fp16 = 64B
        const uint32_t bB = sB_u + (ch & 1) * BUFB + addrB0_rel;
#pragma unroll
        for (int ks = 0; ks < 2; ks++) {
            uint32_t a0, a1, a2, a3, a4, a5, a6, a7;
            ldsm4(a0, a1, a2, a3, aK + ks * 32);
            ldsm4(a4, a5, a6, a7, aK + 16 * LDA * 2 + ks * 32);
#pragma unroll
            for (int f = 0; f < 4; f++) {
                uint32_t b0, b1, b2, b3;
                ldsm4(b0, b1, b2, b3, bB + f * (16 * LDB * 2) + ks * 32);
                mma16816(acc[0][2 * f],     a0, a1, a2, a3, b0, b1);
                mma16816(acc[0][2 * f + 1], a0, a1, a2, a3, b2, b3);
                mma16816(acc[1][2 * f],     a4, a5, a6, a7, b0, b1);
                mma16816(acc[1][2 * f + 1], a4, a5, a6, a7, b2, b3);
            }
        }

        // epilogue for completed 256-col block
        if (kc == 15) {
#pragma unroll
            for (int mi = 0; mi < 2; mi++)
#pragma unroll
                for (int ni = 0; ni < 8; ni++) {
                    const int col = nc * 256 + n0w + ni * 8 + tq * 2;
                    const float w0 = s_w2q[col], w1 = s_w2q[col + 1];
                    const float v0 = s_V[col],   v1 = s_V[col + 1];
                    const float* c = acc[mi][ni];
                    rsum[mi * 2 + 0] += v0 * tanh_approx(c[0] + w0) + v1 * tanh_approx(c[1] + w1);
                    rsum[mi * 2 + 1] += v0 * tanh_approx(c[2] + w0) + v1 * tanh_approx(c[3] + w1);
                }
        }

        if (ch + 1 < NCH) {
            CP_WAIT0();                              // B chunk ch+1 landed
            __syncthreads();
        }
    }

    // quad reduce (tq lanes), then cross-colgroup reduce via smem
#pragma unroll
    for (int j = 0; j < 4; j++) {
        rsum[j] += __shfl_xor_sync(0xFFFFFFFF, rsum[j], 1);
        rsum[j] += __shfl_xor_sync(0xFFFFFFFF, rsum[j], 2);
    }
    __syncthreads();
    if (tq == 0) {
#pragma unroll
        for (int mi = 0; mi < 2; mi++)
#pragma unroll
            for (int h = 0; h < 2; h++)
                s_red[cgw * 64 + m0 + mi * 16 + h * 8 + gq] = rsum[mi * 2 + h];
    }
    __syncthreads();
    if (tid < 64)
        g_u[row0 + tid] = (s_red[tid] + s_red[64 + tid])
                        + (s_red[128 + tid] + s_red[192 + tid]);
}

// ==================== kernel: masked softmax + candidate collection ====================
__global__ void __launch_bounds__(256)
tail1_kernel(const int* __restrict__ mask, float* __restrict__ out_a) {
    int b = blockIdx.x, tid = threadIdx.x;           // 256 threads
    __shared__ float red[256];
    __shared__ int   ncand;

    const float* ub = g_u + b * NT;
    const int* mb = mask + b * NT;
    float* ab = out_a + b * NT;

    float mx = -3.4e38f;
    for (int t = tid; t < NT; t += 256) {
        float um = ub[t] + (mb[t] ? 0.f : -1e20f);
        mx = fmaxf(mx, um);
    }
    red[tid] = mx; __syncthreads();
    for (int s = 128; s > 0; s >>= 1) { if (tid < s) red[tid] = fmaxf(red[tid], red[tid + s]); __syncthreads(); }
    mx = red[0];
    if (tid == 0) ncand = 0;
    __syncthreads();

    float sum = 0.f;
    for (int t = tid; t < NT; t += 256) {
        float um = ub[t] + (mb[t] ? 0.f : -1e20f);
        float e = expf(um - mx);
        ab[t] = e;
        sum += e;
        if (um > mx - 0.01f) {                       // fp16 GEMM u-error ~1e-3 << 0.01
            int p = atomicAdd(&ncand, 1);
            if (p < MAXC) g_cand[b * MAXC + p] = t;
        }
    }
    red[tid] = sum; __syncthreads();
    for (int s = 128; s > 0; s >>= 1) { if (tid < s) red[tid] += red[tid + s]; __syncthreads(); }
    float inv = 1.0f / red[0];
    __syncthreads();
    for (int t = tid; t < NT; t += 256) ab[t] *= inv;
    if (tid == 0) g_ncand[b] = min(ncand, MAXC);
}

// ==================== kernel: exact-fp32 candidate re-score (8 n-slices/cand) =====
__global__ void __launch_bounds__(64)
tail2_kernel(const float* __restrict__ value, const float* __restrict__ W1,
             const float* __restrict__ Vvec) {
    const int b = blockIdx.x, ci = blockIdx.y, sl = blockIdx.z, tx = threadIdx.x;
    if (ci >= g_ncand[b]) return;
    const int t = g_cand[b * MAXC + ci];

    __shared__ float sval[ND];
    __shared__ float wsum[2];

    for (int i = tx; i < ND; i += 64)
        sval[i] = value[((size_t)b * NT + t) * ND + i];
    __syncthreads();

    const int n = sl * 64 + tx;
    float s1 = 0.f;
#pragma unroll 8
    for (int d = 0; d < ND; d++) s1 += sval[d] * W1[(size_t)d * NU + n];
    float p = Vvec[n] * tanhf(s1 + g_w2q[b * NU + n]);

#pragma unroll
    for (int o = 16; o > 0; o >>= 1) p += __shfl_xor_sync(0xFFFFFFFF, p, o);
    if ((tx & 31) == 0) wsum[tx >> 5] = p;
    __syncthreads();
    if (tx == 0) atomicAdd(&g_score[b * MAXC + ci], wsum[0] + wsum[1]);
}

// ==================== kernel: pack scores -> best key ====================
__global__ void tail2b_kernel() {
    int i = threadIdx.x;                             // 512 threads: (b, ci)
    int b = i >> 4, ci = i & 15;
    if (ci < g_ncand[b])
        atomicMax(&g_best[b], pack_key(g_score[i], g_cand[i]));
}

// ==================== kernel: gather context ====================
__global__ void __launch_bounds__(512)
tail3_kernel(const float* __restrict__ value, float* __restrict__ out_ctx) {
    const int b = blockIdx.x, tid = threadIdx.x;     // 512 threads
    const int t = 2047 - (int)(g_best[b] & 0xFFFFFFFFull);
    out_ctx[b * ND + tid] = value[((size_t)b * NT + t) * ND + tid];
}

// ==================== launch ====================
extern "C" void kernel_launch(void* const* d_in, const int* in_sizes, int n_in,
                              void* d_out, int out_size) {
    const float* value = (const float*)d_in[0];   // [32, 2048, 512]
    const float* query = (const float*)d_in[1];   // [32, 512]
    const int*   mask  = (const int*)d_in[2];     // [32, 2048]
    const float* W1    = (const float*)d_in[3];   // [512, 512]
    const float* W2    = (const float*)d_in[4];   // [512, 512]
    const float* Vv    = (const float*)d_in[5];   // [512]

    float* out     = (float*)d_out;
    float* out_ctx = out;                         // context [32, 512] first
    float* out_a   = out + NBATCH * ND;           // then a [32, 2048]

    cudaFuncSetAttribute(attn_main, cudaFuncAttributeMaxDynamicSharedMemorySize, SMEM_BYTES);

    prep_w1t<<<dim3(NU / 32, ND / 32), dim3(32, 8)>>>(W1);          // idx 0
    init_kernel<<<32, 512>>>();                                      // idx 1
    prep_w2q<<<dim3(8, 4), 64>>>(query, W2);                         // idx 2
    attn_main<<<(NBATCH * NT) / 64, 256, SMEM_BYTES>>>(value, Vv);   // idx 3 (profiled)
    tail1_kernel<<<NBATCH, 256>>>(mask, out_a);
    tail2_kernel<<<dim3(NBATCH, MAXC, 8), 64>>>(value, W1, Vv);
    tail2b_kernel<<<1, 512>>>();
    tail3_kernel<<<NBATCH, 512>>>(value, out_ctx);
}